// round 15
// baseline (speedup 1.0000x reference)
#include <cuda_runtime.h>
#include <cstdint>

// ---------------- problem constants ----------------
#define NQ      13294
#define BS      2
#define M_TOT   (BS * NQ)      // 26588
#define EMBED   256
#define HEADS   8
#define LEVELS  4
#define POINTS  4
#define NPROJ   640            // 256 (value) + 256 (off) + 128 (attn)

__device__ __constant__ int c_Wl[LEVELS]    = {100, 50, 25, 13};
__device__ __constant__ int c_Hl[LEVELS]    = {100, 50, 25, 13};
__device__ __constant__ int c_start[LEVELS] = {0, 10000, 12500, 13125};

// ---------------- scratch ----------------
__device__ float g_proj   [(size_t)M_TOT * NPROJ];
__device__ float g_acc    [(size_t)M_TOT * EMBED];
__device__ float g_query_t[(size_t)M_TOT * EMBED];
__device__ float g_Wcat   [(size_t)EMBED * NPROJ];
__device__ float g_Wout_t [(size_t)EMBED * EMBED];
__device__ float g_bcat   [NPROJ];

__device__ __forceinline__ uint32_t f2tf32(float f) {
    uint32_t r;
    asm("cvt.rna.tf32.f32 %0, %1;" : "=r"(r) : "f"(f));
    return r;
}
__device__ __forceinline__ float tf32r(float f) { return __uint_as_float(f2tf32(f)); }
__device__ __forceinline__ float4 tf32r4(float4 v) {
    v.x = tf32r(v.x); v.y = tf32r(v.y); v.z = tf32r(v.z); v.w = tf32r(v.w);
    return v;
}

// ---------------- fused prep ----------------
#define N4Q    (M_TOT * EMBED / 4)
#define N4WCAT (EMBED * NPROJ / 4)
#define N4WOUT (EMBED * EMBED / 4)

__global__ void prep_all_kernel(const float* __restrict__ query,
                                const float* __restrict__ Wv, const float* __restrict__ Woff,
                                const float* __restrict__ Wat, const float* __restrict__ Wout,
                                const float* __restrict__ bv, const float* __restrict__ boff,
                                const float* __restrict__ bat,
                                float* __restrict__ qt, float* __restrict__ Wcat,
                                float* __restrict__ Wout_t, float* __restrict__ bcat) {
    const int idx = blockIdx.x * blockDim.x + threadIdx.x;

    if (idx < N4Q) {
        reinterpret_cast<float4*>(qt)[idx] =
            tf32r4(reinterpret_cast<const float4*>(query)[idx]);
    }
    if (idx < N4WCAT) {
        const int k  = idx / (NPROJ / 4);
        const int c4 = idx - k * (NPROJ / 4);
        const int n  = c4 * 4;
        float4 v;
        if (n < 256)      v = *reinterpret_cast<const float4*>(Wv   + k * 256 + n);
        else if (n < 512) v = *reinterpret_cast<const float4*>(Woff + k * 256 + (n - 256));
        else              v = *reinterpret_cast<const float4*>(Wat  + k * 128 + (n - 512));
        reinterpret_cast<float4*>(Wcat)[idx] = tf32r4(v);
    }
    if (idx < N4WOUT) {
        reinterpret_cast<float4*>(Wout_t)[idx] =
            tf32r4(reinterpret_cast<const float4*>(Wout)[idx]);
    }
    if (idx < NPROJ) {
        float b;
        if (idx < 256)      b = bv  [idx];
        else if (idx < 512) b = boff[idx - 256];
        else                b = bat [idx - 512];
        bcat[idx] = b;
    }
}

// ---------------- tf32 GEMM, templated on M-tile (3-stage, K-chunk 32) ----------------
#define GTK     32
#define NKS     (EMBED / GTK)    // 8
#define LDA     36
#define LDB     136
#define STAGES  3
#define B_STG   (GTK * LDB)

__device__ __forceinline__ uint32_t smem_u32(const void* p) {
    return (uint32_t)__cvta_generic_to_shared(p);
}
__device__ __forceinline__ void cp_async16(uint32_t dst, const void* src, uint32_t sz) {
    asm volatile("cp.async.cg.shared.global [%0], [%1], 16, %2;"
                 :: "r"(dst), "l"(src), "r"(sz));
}

template <int TM>
__global__ void __launch_bounds__(256)
gemm_tf32_kernel(const float* __restrict__ A, int lda,
                 const float* __restrict__ B, int ldb,
                 const float* __restrict__ bias,
                 const float* __restrict__ resid,
                 float* __restrict__ C, int ldc,
                 int M) {
    constexpr int A_STG = TM * LDA;
    constexpr int MT    = TM / 32;          // m-subtiles per warp (4 or 2)
    constexpr int A_CH  = TM * 8 / 256;     // 16B chunks per thread per A stage

    extern __shared__ __align__(16) float smem[];
    float* sA = smem;
    float* sB = smem + STAGES * A_STG;

    const int tid  = threadIdx.x;
    const int wid  = tid >> 5;
    const int lane = tid & 31;
    const int m_w  = (wid >> 2) * (TM / 2);
    const int n_w  = (wid & 3) * 32;
    const int m0   = blockIdx.y * TM;
    const int n0   = blockIdx.x * 128;

    const int grp = lane >> 2;
    const int tig = lane & 3;

    float acc[MT][4][4];
#pragma unroll
    for (int i = 0; i < MT; i++)
#pragma unroll
        for (int j = 0; j < 4; j++)
#pragma unroll
            for (int r = 0; r < 4; r++) acc[i][j][r] = 0.f;

    auto load_stage = [&](int ks) {
        const int buf = ks % STAGES;
        const int k0  = ks * GTK;
        float* dA = sA + buf * A_STG;
        float* dB = sB + buf * B_STG;
#pragma unroll
        for (int c = 0; c < A_CH; c++) {
            const int ch  = tid + c * 256;
            const int row = ch >> 3;
            const int col = ch & 7;
            const int gm  = m0 + row;
            cp_async16(smem_u32(&dA[row * LDA + col * 4]),
                       A + (size_t)gm * lda + k0 + col * 4, gm < M ? 16u : 0u);
        }
#pragma unroll
        for (int c = 0; c < 4; c++) {
            const int ch  = tid + c * 256;
            const int row = ch >> 5;
            const int col = ch & 31;
            cp_async16(smem_u32(&dB[row * LDB + col * 4]),
                       B + (size_t)(k0 + row) * ldb + n0 + col * 4, 16u);
        }
    };

#pragma unroll
    for (int s = 0; s < STAGES - 1; s++) {
        load_stage(s);
        asm volatile("cp.async.commit_group;" ::: "memory");
    }

    auto load_frags = [&](const float* cA, const float* cB, int kb,
                          uint32_t af[MT][4], uint32_t bf[4][2]) {
#pragma unroll
        for (int mt = 0; mt < MT; mt++) {
            const int mrow = m_w + mt * 16 + grp;
            af[mt][0] = __float_as_uint(cA[ mrow      * LDA + kb + tig]);
            af[mt][1] = __float_as_uint(cA[(mrow + 8) * LDA + kb + tig]);
            af[mt][2] = __float_as_uint(cA[ mrow      * LDA + kb + tig + 4]);
            af[mt][3] = __float_as_uint(cA[(mrow + 8) * LDA + kb + tig + 4]);
        }
#pragma unroll
        for (int nt = 0; nt < 4; nt++) {
            const int ncol = n_w + nt * 8 + grp;
            bf[nt][0] = __float_as_uint(cB[(kb + tig)     * LDB + ncol]);
            bf[nt][1] = __float_as_uint(cB[(kb + tig + 4) * LDB + ncol]);
        }
    };
    auto do_mma = [&](uint32_t af[MT][4], uint32_t bf[4][2]) {
#pragma unroll
        for (int mt = 0; mt < MT; mt++)
#pragma unroll
            for (int nt = 0; nt < 4; nt++) {
                asm volatile(
                    "mma.sync.aligned.m16n8k8.row.col.f32.tf32.tf32.f32 "
                    "{%0,%1,%2,%3}, {%4,%5,%6,%7}, {%8,%9}, {%0,%1,%2,%3};"
                    : "+f"(acc[mt][nt][0]), "+f"(acc[mt][nt][1]),
                      "+f"(acc[mt][nt][2]), "+f"(acc[mt][nt][3])
                    : "r"(af[mt][0]), "r"(af[mt][1]), "r"(af[mt][2]), "r"(af[mt][3]),
                      "r"(bf[nt][0]), "r"(bf[nt][1]));
            }
    };

    uint32_t af2[2][MT][4], bf2[2][4][2];

    for (int ks = 0; ks < NKS; ks++) {
        asm volatile("cp.async.wait_group 1;" ::: "memory");
        __syncthreads();

        if (ks + STAGES - 1 < NKS) load_stage(ks + STAGES - 1);
        asm volatile("cp.async.commit_group;" ::: "memory");

        const float* cA = sA + (ks % STAGES) * A_STG;
        const float* cB = sB + (ks % STAGES) * B_STG;

        load_frags(cA, cB, 0, af2[0], bf2[0]);
#pragma unroll
        for (int sub = 0; sub < 4; sub++) {
            const int p = sub & 1;
            if (sub < 3) load_frags(cA, cB, (sub + 1) * 8, af2[p ^ 1], bf2[p ^ 1]);
            do_mma(af2[p], bf2[p]);
        }
    }

#pragma unroll
    for (int mt = 0; mt < MT; mt++) {
#pragma unroll
        for (int nt = 0; nt < 4; nt++) {
            const int gm = m0 + m_w + mt * 16 + grp;
            const int gn = n0 + n_w + nt * 8 + tig * 2;
            const float b0 = bias[gn], b1 = bias[gn + 1];
            if (gm < M) {
                float v0 = acc[mt][nt][0] + b0;
                float v1 = acc[mt][nt][1] + b1;
                if (resid) {
                    v0 += resid[(size_t)gm * ldc + gn];
                    v1 += resid[(size_t)gm * ldc + gn + 1];
                }
                C[(size_t)gm * ldc + gn]     = v0;
                C[(size_t)gm * ldc + gn + 1] = v1;
            }
            if (gm + 8 < M) {
                float v2 = acc[mt][nt][2] + b0;
                float v3 = acc[mt][nt][3] + b1;
                if (resid) {
                    v2 += resid[(size_t)(gm + 8) * ldc + gn];
                    v3 += resid[(size_t)(gm + 8) * ldc + gn + 1];
                }
                C[(size_t)(gm + 8) * ldc + gn]     = v2;
                C[(size_t)(gm + 8) * ldc + gn + 1] = v3;
            }
        }
    }
}

#define SMEM_GEMM128 ((STAGES * (128 * LDA + B_STG)) * 4)   // 107520
#define SMEM_GEMM64  ((STAGES * ( 64 * LDA + B_STG)) * 4)   //  79872

// ---------------- sampling kernel (R14: 2 rows/block, smem-batched IW) ----------------
struct IW { int idx; float w; };

__global__ void msda_sample_kernel(const float* __restrict__ ref,
                                   const float* __restrict__ proj,
                                   float* __restrict__ acc) {
    __shared__ IW s_iw[2][128][4];

    const int r0  = blockIdx.x * 2;
    const int tid = threadIdx.x;

    {
        const int rr   = tid >> 7;
        const int t    = tid & 127;
        const int row  = r0 + rr;
        const int head = t >> 4;
        const int i    = t & 15;
        const int l    = i >> 2;
        const int Wl = c_Wl[l], Hl = c_Hl[l];
        const int vbase = (row >= NQ) ? NQ : 0;

        float lg = __ldg(proj + (size_t)row * NPROJ + 512 + t);
        float mx = lg;
#pragma unroll
        for (int o = 8; o >= 1; o >>= 1)
            mx = fmaxf(mx, __shfl_xor_sync(0xffffffffu, mx, o, 16));
        float e = __expf(lg - mx);
        float s = e;
#pragma unroll
        for (int o = 8; o >= 1; o >>= 1)
            s += __shfl_xor_sync(0xffffffffu, s, o, 16);
        const float w = e * __frcp_rn(s);

        const float rx = __ldg(ref + (size_t)row * 8 + 2 * l + 0) * (float)Wl - 0.5f;
        const float ry = __ldg(ref + (size_t)row * 8 + 2 * l + 1) * (float)Hl - 0.5f;
        const float2 o2 = *reinterpret_cast<const float2*>(
            proj + (size_t)row * NPROJ + 256 + head * 32 + 2 * i);
        const float x = rx + o2.x;
        const float y = ry + o2.y;

        const float xf = floorf(x), yf = floorf(y);
        const int x0 = (int)xf, y0 = (int)yf;
        const float lx = x - xf, ly = y - yf;

        const bool yin0 = (y0 >= 0) & (y0 < Hl);
        const bool yin1 = (y0 + 1 >= 0) & (y0 + 1 < Hl);
        const bool xin0 = (x0 >= 0) & (x0 < Wl);
        const bool xin1 = (x0 + 1 >= 0) & (x0 + 1 < Wl);

        const int base = vbase + c_start[l];
        const int rA = (base + y0 * Wl) * NPROJ + head * 32;
        const int rB = rA + Wl * NPROJ;

        IW c0, c1, c2, c3;
        c0.idx = (yin0 && xin0) ? rA + x0 * NPROJ       : -1;
        c1.idx = (yin0 && xin1) ? rA + (x0 + 1) * NPROJ : -1;
        c2.idx = (yin1 && xin0) ? rB + x0 * NPROJ       : -1;
        c3.idx = (yin1 && xin1) ? rB + (x0 + 1) * NPROJ : -1;
        c0.w = (1.f - ly) * (1.f - lx) * w;
        c1.w = (1.f - ly) * lx * w;
        c2.w = ly * (1.f - lx) * w;
        c3.w = ly * lx * w;
        s_iw[rr][t][0] = c0;
        s_iw[rr][t][1] = c1;
        s_iw[rr][t][2] = c2;
        s_iw[rr][t][3] = c3;
    }
    __syncthreads();

    const int head = tid >> 5;
    const int lane = tid & 31;
    const int g    = lane >> 3;
    const int sub  = lane & 7;

#pragma unroll
    for (int rr = 0; rr < 2; rr++) {
        const int row = r0 + rr;
        float4 a = make_float4(0.f, 0.f, 0.f, 0.f);

#pragma unroll
        for (int b = 0; b < 2; b++) {
            IW p[8];
#pragma unroll
            for (int j = 0; j < 8; j++)
                p[j] = s_iw[rr][head * 16 + b * 8 + j][g];

            float4 v[8];
#pragma unroll
            for (int j = 0; j < 8; j++)
                v[j] = (p[j].idx >= 0)
                     ? *reinterpret_cast<const float4*>(proj + p[j].idx + (sub << 2))
                     : make_float4(0.f, 0.f, 0.f, 0.f);
#pragma unroll
            for (int j = 0; j < 8; j++) {
                a.x = fmaf(p[j].w, v[j].x, a.x);
                a.y = fmaf(p[j].w, v[j].y, a.y);
                a.z = fmaf(p[j].w, v[j].z, a.z);
                a.w = fmaf(p[j].w, v[j].w, a.w);
            }
        }
#pragma unroll
        for (int o = 8; o <= 16; o <<= 1) {
            a.x += __shfl_xor_sync(0xffffffffu, a.x, o);
            a.y += __shfl_xor_sync(0xffffffffu, a.y, o);
            a.z += __shfl_xor_sync(0xffffffffu, a.z, o);
            a.w += __shfl_xor_sync(0xffffffffu, a.w, o);
        }
        if (lane < 8) {
            a = tf32r4(a);
            *reinterpret_cast<float4*>(acc + (size_t)row * 256 + head * 32 + (sub << 2)) = a;
        }
    }
}

// ---------------- launch ----------------
extern "C" void kernel_launch(void* const* d_in, const int* in_sizes, int n_in,
                              void* d_out, int out_size) {
    const float* query  = (const float*)d_in[0];
    const float* refpts = (const float*)d_in[1];
    const float* Wv   = (const float*)d_in[3];
    const float* bv   = (const float*)d_in[4];
    const float* Woff = (const float*)d_in[5];
    const float* boff = (const float*)d_in[6];
    const float* Wat  = (const float*)d_in[7];
    const float* bat  = (const float*)d_in[8];
    const float* Wout = (const float*)d_in[9];
    const float* bout = (const float*)d_in[10];
    float* out = (float*)d_out;

    float *p_proj, *p_acc, *p_qt, *p_Wcat, *p_Wout_t, *p_bcat;
    cudaGetSymbolAddress((void**)&p_proj,   g_proj);
    cudaGetSymbolAddress((void**)&p_acc,    g_acc);
    cudaGetSymbolAddress((void**)&p_qt,     g_query_t);
    cudaGetSymbolAddress((void**)&p_Wcat,   g_Wcat);
    cudaGetSymbolAddress((void**)&p_Wout_t, g_Wout_t);
    cudaGetSymbolAddress((void**)&p_bcat,   g_bcat);

    cudaFuncSetAttribute(gemm_tf32_kernel<128>,
                         cudaFuncAttributeMaxDynamicSharedMemorySize, SMEM_GEMM128);
    cudaFuncSetAttribute(gemm_tf32_kernel<64>,
                         cudaFuncAttributeMaxDynamicSharedMemorySize, SMEM_GEMM64);

    const int M    = M_TOT;
    const int gy   = (M + 127) / 128;   // 208
    const int gy64 = (M + 63) / 64;     // 416

    // single fused prep launch
    prep_all_kernel<<<(N4Q + 255) / 256, 256>>>(query, Wv, Woff, Wat, Wout,
                                                bv, boff, bat,
                                                p_qt, p_Wcat, p_Wout_t, p_bcat);

    // fused projection GEMM: M x 640 (TM=128; 1040 blocks)
    gemm_tf32_kernel<128><<<dim3(NPROJ / 128, gy), 256, SMEM_GEMM128>>>(
        p_qt, EMBED, p_Wcat, NPROJ, p_bcat, nullptr, p_proj, NPROJ, M);

    // deformable sampling (2 rows per block)
    msda_sample_kernel<<<M / 2, HEADS * 32>>>(refpts, p_proj, p_acc);

    // output projection + bias + residual (TM=64; 832 blocks -> 2.81 waves)
    gemm_tf32_kernel<64><<<dim3(2, gy64), 256, SMEM_GEMM64>>>(
        p_acc, EMBED, p_Wout_t, EMBED, bout, query, out, EMBED, M);
}

// round 16
// speedup vs baseline: 1.0208x; 1.0208x over previous
#include <cuda_runtime.h>
#include <cuda_fp16.h>
#include <cstdint>

// ---------------- problem constants ----------------
#define NQ      13294
#define BS      2
#define M_TOT   (BS * NQ)      // 26588
#define EMBED   256
#define HEADS   8
#define LEVELS  4
#define POINTS  4
#define NPROJ   640            // 256 (value) + 256 (off) + 128 (attn)

__device__ __constant__ int c_Wl[LEVELS]    = {100, 50, 25, 13};
__device__ __constant__ int c_Hl[LEVELS]    = {100, 50, 25, 13};
__device__ __constant__ int c_start[LEVELS] = {0, 10000, 12500, 13125};

// ---------------- scratch ----------------
__device__ float  g_proj   [(size_t)M_TOT * NPROJ];
__device__ __half g_val16  [(size_t)M_TOT * EMBED];   // fp16 mirror of value cols
__device__ float  g_acc    [(size_t)M_TOT * EMBED];
__device__ float  g_query_t[(size_t)M_TOT * EMBED];
__device__ float  g_Wcat   [(size_t)EMBED * NPROJ];
__device__ float  g_Wout_t [(size_t)EMBED * EMBED];
__device__ float  g_bcat   [NPROJ];

__device__ __forceinline__ uint32_t f2tf32(float f) {
    uint32_t r;
    asm("cvt.rna.tf32.f32 %0, %1;" : "=r"(r) : "f"(f));
    return r;
}
__device__ __forceinline__ float tf32r(float f) { return __uint_as_float(f2tf32(f)); }
__device__ __forceinline__ float4 tf32r4(float4 v) {
    v.x = tf32r(v.x); v.y = tf32r(v.y); v.z = tf32r(v.z); v.w = tf32r(v.w);
    return v;
}

// ---------------- fused prep ----------------
#define N4Q    (M_TOT * EMBED / 4)
#define N4WCAT (EMBED * NPROJ / 4)
#define N4WOUT (EMBED * EMBED / 4)

__global__ void prep_all_kernel(const float* __restrict__ query,
                                const float* __restrict__ Wv, const float* __restrict__ Woff,
                                const float* __restrict__ Wat, const float* __restrict__ Wout,
                                const float* __restrict__ bv, const float* __restrict__ boff,
                                const float* __restrict__ bat,
                                float* __restrict__ qt, float* __restrict__ Wcat,
                                float* __restrict__ Wout_t, float* __restrict__ bcat) {
    const int idx = blockIdx.x * blockDim.x + threadIdx.x;

    if (idx < N4Q) {
        reinterpret_cast<float4*>(qt)[idx] =
            tf32r4(reinterpret_cast<const float4*>(query)[idx]);
    }
    if (idx < N4WCAT) {
        const int k  = idx / (NPROJ / 4);
        const int c4 = idx - k * (NPROJ / 4);
        const int n  = c4 * 4;
        float4 v;
        if (n < 256)      v = *reinterpret_cast<const float4*>(Wv   + k * 256 + n);
        else if (n < 512) v = *reinterpret_cast<const float4*>(Woff + k * 256 + (n - 256));
        else              v = *reinterpret_cast<const float4*>(Wat  + k * 128 + (n - 512));
        reinterpret_cast<float4*>(Wcat)[idx] = tf32r4(v);
    }
    if (idx < N4WOUT) {
        reinterpret_cast<float4*>(Wout_t)[idx] =
            tf32r4(reinterpret_cast<const float4*>(Wout)[idx]);
    }
    if (idx < NPROJ) {
        float b;
        if (idx < 256)      b = bv  [idx];
        else if (idx < 512) b = boff[idx - 256];
        else                b = bat [idx - 512];
        bcat[idx] = b;
    }
}

// ---------------- tf32 GEMM (3-stage, K-chunk 32, TM=128) ----------------
#define GTK     32
#define NKS     (EMBED / GTK)    // 8
#define LDA     36
#define LDB     136
#define STAGES  3
#define A_STG   (128 * LDA)
#define B_STG   (GTK * LDB)
#define SMEM_GEMM ((STAGES * (A_STG + B_STG)) * 4)   // 107520

__device__ __forceinline__ uint32_t smem_u32(const void* p) {
    return (uint32_t)__cvta_generic_to_shared(p);
}
__device__ __forceinline__ void cp_async16(uint32_t dst, const void* src, uint32_t sz) {
    asm volatile("cp.async.cg.shared.global [%0], [%1], 16, %2;"
                 :: "r"(dst), "l"(src), "r"(sz));
}

__global__ void __launch_bounds__(256)
gemm_tf32_kernel(const float* __restrict__ A, int lda,
                 const float* __restrict__ B, int ldb,
                 const float* __restrict__ bias,
                 const float* __restrict__ resid,
                 float* __restrict__ C, int ldc,
                 __half* __restrict__ v16,      // optional fp16 mirror for cols<256
                 int M) {
    extern __shared__ __align__(16) float smem[];
    float* sA = smem;
    float* sB = smem + STAGES * A_STG;

    const int tid  = threadIdx.x;
    const int wid  = tid >> 5;
    const int lane = tid & 31;
    const int m_w  = (wid >> 2) * 64;
    const int n_w  = (wid & 3) * 32;
    const int m0   = blockIdx.y * 128;
    const int n0   = blockIdx.x * 128;

    const int grp = lane >> 2;
    const int tig = lane & 3;

    float acc[4][4][4];
#pragma unroll
    for (int i = 0; i < 4; i++)
#pragma unroll
        for (int j = 0; j < 4; j++)
#pragma unroll
            for (int r = 0; r < 4; r++) acc[i][j][r] = 0.f;

    auto load_stage = [&](int ks) {
        const int buf = ks % STAGES;
        const int k0  = ks * GTK;
        float* dA = sA + buf * A_STG;
        float* dB = sB + buf * B_STG;
#pragma unroll
        for (int c = 0; c < 4; c++) {
            const int ch  = tid + c * 256;
            const int row = ch >> 3;
            const int col = ch & 7;
            const int gm  = m0 + row;
            cp_async16(smem_u32(&dA[row * LDA + col * 4]),
                       A + (size_t)gm * lda + k0 + col * 4, gm < M ? 16u : 0u);
        }
#pragma unroll
        for (int c = 0; c < 4; c++) {
            const int ch  = tid + c * 256;
            const int row = ch >> 5;
            const int col = ch & 31;
            cp_async16(smem_u32(&dB[row * LDB + col * 4]),
                       B + (size_t)(k0 + row) * ldb + n0 + col * 4, 16u);
        }
    };

#pragma unroll
    for (int s = 0; s < STAGES - 1; s++) {
        load_stage(s);
        asm volatile("cp.async.commit_group;" ::: "memory");
    }

    auto load_frags = [&](const float* cA, const float* cB, int kb,
                          uint32_t af[4][4], uint32_t bf[4][2]) {
#pragma unroll
        for (int mt = 0; mt < 4; mt++) {
            const int mrow = m_w + mt * 16 + grp;
            af[mt][0] = __float_as_uint(cA[ mrow      * LDA + kb + tig]);
            af[mt][1] = __float_as_uint(cA[(mrow + 8) * LDA + kb + tig]);
            af[mt][2] = __float_as_uint(cA[ mrow      * LDA + kb + tig + 4]);
            af[mt][3] = __float_as_uint(cA[(mrow + 8) * LDA + kb + tig + 4]);
        }
#pragma unroll
        for (int nt = 0; nt < 4; nt++) {
            const int ncol = n_w + nt * 8 + grp;
            bf[nt][0] = __float_as_uint(cB[(kb + tig)     * LDB + ncol]);
            bf[nt][1] = __float_as_uint(cB[(kb + tig + 4) * LDB + ncol]);
        }
    };
    auto do_mma = [&](uint32_t af[4][4], uint32_t bf[4][2]) {
#pragma unroll
        for (int mt = 0; mt < 4; mt++)
#pragma unroll
            for (int nt = 0; nt < 4; nt++) {
                asm volatile(
                    "mma.sync.aligned.m16n8k8.row.col.f32.tf32.tf32.f32 "
                    "{%0,%1,%2,%3}, {%4,%5,%6,%7}, {%8,%9}, {%0,%1,%2,%3};"
                    : "+f"(acc[mt][nt][0]), "+f"(acc[mt][nt][1]),
                      "+f"(acc[mt][nt][2]), "+f"(acc[mt][nt][3])
                    : "r"(af[mt][0]), "r"(af[mt][1]), "r"(af[mt][2]), "r"(af[mt][3]),
                      "r"(bf[nt][0]), "r"(bf[nt][1]));
            }
    };

    uint32_t af2[2][4][4], bf2[2][4][2];

    for (int ks = 0; ks < NKS; ks++) {
        asm volatile("cp.async.wait_group 1;" ::: "memory");
        __syncthreads();

        if (ks + STAGES - 1 < NKS) load_stage(ks + STAGES - 1);
        asm volatile("cp.async.commit_group;" ::: "memory");

        const float* cA = sA + (ks % STAGES) * A_STG;
        const float* cB = sB + (ks % STAGES) * B_STG;

        load_frags(cA, cB, 0, af2[0], bf2[0]);
#pragma unroll
        for (int sub = 0; sub < 4; sub++) {
            const int p = sub & 1;
            if (sub < 3) load_frags(cA, cB, (sub + 1) * 8, af2[p ^ 1], bf2[p ^ 1]);
            do_mma(af2[p], bf2[p]);
        }
    }

#pragma unroll
    for (int mt = 0; mt < 4; mt++) {
#pragma unroll
        for (int nt = 0; nt < 4; nt++) {
            const int gm = m0 + m_w + mt * 16 + grp;
            const int gn = n0 + n_w + nt * 8 + tig * 2;
            const float b0 = bias[gn], b1 = bias[gn + 1];
            if (gm < M) {
                float v0 = acc[mt][nt][0] + b0;
                float v1 = acc[mt][nt][1] + b1;
                if (resid) {
                    v0 += resid[(size_t)gm * ldc + gn];
                    v1 += resid[(size_t)gm * ldc + gn + 1];
                }
                C[(size_t)gm * ldc + gn]     = v0;
                C[(size_t)gm * ldc + gn + 1] = v1;
                if (v16 && gn < 256)
                    *reinterpret_cast<__half2*>(v16 + (size_t)gm * 256 + gn) =
                        __floats2half2_rn(v0, v1);
            }
            if (gm + 8 < M) {
                float v2 = acc[mt][nt][2] + b0;
                float v3 = acc[mt][nt][3] + b1;
                if (resid) {
                    v2 += resid[(size_t)(gm + 8) * ldc + gn];
                    v3 += resid[(size_t)(gm + 8) * ldc + gn + 1];
                }
                C[(size_t)(gm + 8) * ldc + gn]     = v2;
                C[(size_t)(gm + 8) * ldc + gn + 1] = v3;
                if (v16 && gn < 256)
                    *reinterpret_cast<__half2*>(v16 + (size_t)(gm + 8) * 256 + gn) =
                        __floats2half2_rn(v2, v3);
            }
        }
    }
}

// ---------------- sampling kernel: 2 rows/block, fp16 value gather ----------------
struct IW { int idx; float w; };

__global__ void msda_sample_kernel(const float* __restrict__ ref,
                                   const float* __restrict__ proj,
                                   const __half* __restrict__ val16,
                                   float* __restrict__ acc) {
    __shared__ IW s_iw[2][128][4];

    const int r0  = blockIdx.x * 2;
    const int tid = threadIdx.x;

    // ---- scalar phase: 256 threads = 2 rows x 128 (head,point) tasks ----
    {
        const int rr   = tid >> 7;
        const int t    = tid & 127;
        const int row  = r0 + rr;
        const int head = t >> 4;
        const int i    = t & 15;
        const int l    = i >> 2;
        const int Wl = c_Wl[l], Hl = c_Hl[l];
        const int vbase = (row >= NQ) ? NQ : 0;

        float lg = __ldg(proj + (size_t)row * NPROJ + 512 + t);
        float mx = lg;
#pragma unroll
        for (int o = 8; o >= 1; o >>= 1)
            mx = fmaxf(mx, __shfl_xor_sync(0xffffffffu, mx, o, 16));
        float e = __expf(lg - mx);
        float s = e;
#pragma unroll
        for (int o = 8; o >= 1; o >>= 1)
            s += __shfl_xor_sync(0xffffffffu, s, o, 16);
        const float w = e * __frcp_rn(s);

        const float rx = __ldg(ref + (size_t)row * 8 + 2 * l + 0) * (float)Wl - 0.5f;
        const float ry = __ldg(ref + (size_t)row * 8 + 2 * l + 1) * (float)Hl - 0.5f;
        const float2 o2 = *reinterpret_cast<const float2*>(
            proj + (size_t)row * NPROJ + 256 + head * 32 + 2 * i);
        const float x = rx + o2.x;
        const float y = ry + o2.y;

        const float xf = floorf(x), yf = floorf(y);
        const int x0 = (int)xf, y0 = (int)yf;
        const float lx = x - xf, ly = y - yf;

        const bool yin0 = (y0 >= 0) & (y0 < Hl);
        const bool yin1 = (y0 + 1 >= 0) & (y0 + 1 < Hl);
        const bool xin0 = (x0 >= 0) & (x0 < Wl);
        const bool xin1 = (x0 + 1 >= 0) & (x0 + 1 < Wl);

        const int base = vbase + c_start[l];
        // index into val16 (half units, row stride 256)
        const int rA = (base + y0 * Wl) * 256 + head * 32;
        const int rB = rA + Wl * 256;

        IW c0, c1, c2, c3;
        c0.idx = (yin0 && xin0) ? rA + x0 * 256       : -1;
        c1.idx = (yin0 && xin1) ? rA + (x0 + 1) * 256 : -1;
        c2.idx = (yin1 && xin0) ? rB + x0 * 256       : -1;
        c3.idx = (yin1 && xin1) ? rB + (x0 + 1) * 256 : -1;
        c0.w = (1.f - ly) * (1.f - lx) * w;
        c1.w = (1.f - ly) * lx * w;
        c2.w = ly * (1.f - lx) * w;
        c3.w = ly * lx * w;
        s_iw[rr][t][0] = c0;
        s_iw[rr][t][1] = c1;
        s_iw[rr][t][2] = c2;
        s_iw[rr][t][3] = c3;
    }
    __syncthreads();

    // ---- gather phase: warp = head; both rows; fp16 loads (8B/lane/corner) ----
    const int head = tid >> 5;
    const int lane = tid & 31;
    const int g    = lane >> 3;
    const int sub  = lane & 7;

#pragma unroll
    for (int rr = 0; rr < 2; rr++) {
        const int row = r0 + rr;
        float4 a = make_float4(0.f, 0.f, 0.f, 0.f);

#pragma unroll
        for (int b = 0; b < 2; b++) {
            IW p[8];
#pragma unroll
            for (int j = 0; j < 8; j++)
                p[j] = s_iw[rr][head * 16 + b * 8 + j][g];

            uint2 v[8];
#pragma unroll
            for (int j = 0; j < 8; j++)
                v[j] = (p[j].idx >= 0)
                     ? *reinterpret_cast<const uint2*>(val16 + p[j].idx + (sub << 2))
                     : make_uint2(0u, 0u);
#pragma unroll
            for (int j = 0; j < 8; j++) {
                const float2 f0 = __half22float2(*reinterpret_cast<const __half2*>(&v[j].x));
                const float2 f1 = __half22float2(*reinterpret_cast<const __half2*>(&v[j].y));
                a.x = fmaf(p[j].w, f0.x, a.x);
                a.y = fmaf(p[j].w, f0.y, a.y);
                a.z = fmaf(p[j].w, f1.x, a.z);
                a.w = fmaf(p[j].w, f1.y, a.w);
            }
        }
#pragma unroll
        for (int o = 8; o <= 16; o <<= 1) {
            a.x += __shfl_xor_sync(0xffffffffu, a.x, o);
            a.y += __shfl_xor_sync(0xffffffffu, a.y, o);
            a.z += __shfl_xor_sync(0xffffffffu, a.z, o);
            a.w += __shfl_xor_sync(0xffffffffu, a.w, o);
        }
        if (lane < 8) {
            a = tf32r4(a);
            *reinterpret_cast<float4*>(acc + (size_t)row * 256 + head * 32 + (sub << 2)) = a;
        }
    }
}

// ---------------- launch ----------------
extern "C" void kernel_launch(void* const* d_in, const int* in_sizes, int n_in,
                              void* d_out, int out_size) {
    const float* query  = (const float*)d_in[0];
    const float* refpts = (const float*)d_in[1];
    const float* Wv   = (const float*)d_in[3];
    const float* bv   = (const float*)d_in[4];
    const float* Woff = (const float*)d_in[5];
    const float* boff = (const float*)d_in[6];
    const float* Wat  = (const float*)d_in[7];
    const float* bat  = (const float*)d_in[8];
    const float* Wout = (const float*)d_in[9];
    const float* bout = (const float*)d_in[10];
    float* out = (float*)d_out;

    float *p_proj, *p_acc, *p_qt, *p_Wcat, *p_Wout_t, *p_bcat;
    __half* p_v16;
    cudaGetSymbolAddress((void**)&p_proj,   g_proj);
    cudaGetSymbolAddress((void**)&p_acc,    g_acc);
    cudaGetSymbolAddress((void**)&p_qt,     g_query_t);
    cudaGetSymbolAddress((void**)&p_Wcat,   g_Wcat);
    cudaGetSymbolAddress((void**)&p_Wout_t, g_Wout_t);
    cudaGetSymbolAddress((void**)&p_bcat,   g_bcat);
    cudaGetSymbolAddress((void**)&p_v16,    g_val16);

    cudaFuncSetAttribute(gemm_tf32_kernel,
                         cudaFuncAttributeMaxDynamicSharedMemorySize, SMEM_GEMM);

    const int M  = M_TOT;
    const int gy = (M + 127) / 128;   // 208

    // single fused prep launch
    prep_all_kernel<<<(N4Q + 255) / 256, 256>>>(query, Wv, Woff, Wat, Wout,
                                                bv, boff, bat,
                                                p_qt, p_Wcat, p_Wout_t, p_bcat);

    // fused projection GEMM: M x 640 (+ fp16 value mirror)
    gemm_tf32_kernel<<<dim3(NPROJ / 128, gy), 256, SMEM_GEMM>>>(
        p_qt, EMBED, p_Wcat, NPROJ, p_bcat, nullptr, p_proj, NPROJ, p_v16, M);

    // deformable sampling (2 rows per block, fp16 gathers)
    msda_sample_kernel<<<M / 2, HEADS * 32>>>(refpts, p_proj, p_v16, p_acc);

    // output projection + bias + residual (TM=128, reverted)
    gemm_tf32_kernel<<<dim3(2, gy), 256, SMEM_GEMM>>>(
        p_acc, EMBED, p_Wout_t, EMBED, bout, query, out, EMBED, nullptr, M);
}